// round 15
// baseline (speedup 1.0000x reference)
#include <cuda_runtime.h>
#include <cuda_fp16.h>
#include <stdint.h>

#define T_TOK 1024
#define D_DIM 1024
#define F_DIM 2048
#define E_EXP 32
#define TOPK  4
#define NPAIR (T_TOK * TOPK)
#define MAXW  96

// ---------------- static scratch ----------------
__device__ int     g_cnt[E_EXP];
__device__ int     g_pairs[E_EXP * T_TOK];
__device__ float   g_w[NPAIR];
__device__ __half  g_xh[(size_t)T_TOK * D_DIM];    // x pre-converted fp16 (2MB)
__device__ __half  g_hp[(size_t)NPAIR * F_DIM];    // routed hidden fp16
__device__ __half  g_hsp[(size_t)T_TOK * F_DIM];   // shared hidden fp16
__device__ float   g_y[(size_t)NPAIR * D_DIM];     // routed per-pair down output
__device__ int     g_nwork;
__device__ int     g_work[MAXW];                   // (z<<16)|mt ; z==E_EXP -> shared

// ---------------- helpers ----------------
__device__ __forceinline__ uint32_t smem_u32(const void* p) {
    uint32_t a;
    asm("{ .reg .u64 t; cvta.to.shared.u64 t, %1; cvt.u32.u64 %0, t; }" : "=r"(a) : "l"(p));
    return a;
}
__device__ __forceinline__ void ldm4(uint32_t* r, uint32_t addr) {
    asm volatile("ldmatrix.sync.aligned.m8n8.x4.shared.b16 {%0,%1,%2,%3}, [%4];"
                 : "=r"(r[0]), "=r"(r[1]), "=r"(r[2]), "=r"(r[3]) : "r"(addr));
}
__device__ __forceinline__ void mma16816(float* d, const uint32_t* a, const uint32_t* b) {
    asm volatile("mma.sync.aligned.m16n8k16.row.col.f32.f16.f16.f32 "
                 "{%0,%1,%2,%3}, {%4,%5,%6,%7}, {%8,%9}, {%0,%1,%2,%3};"
                 : "+f"(d[0]), "+f"(d[1]), "+f"(d[2]), "+f"(d[3])
                 : "r"(a[0]), "r"(a[1]), "r"(a[2]), "r"(a[3]), "r"(b[0]), "r"(b[1]));
}
__device__ __forceinline__ uint32_t h2bits(__half2 h) {
    return *reinterpret_cast<uint32_t*>(&h);
}
__device__ __forceinline__ void h16_store4(char* dst, float4 v) {
    __half2 a = __floats2half2_rn(v.x, v.y);
    __half2 b = __floats2half2_rn(v.z, v.w);
    *(uint2*)dst = make_uint2(h2bits(a), h2bits(b));
}

// ---------------- tiny kernels ----------------
__global__ void zero_kernel() {
    if (threadIdx.x < E_EXP) g_cnt[threadIdx.x] = 0;
}

// x -> fp16 prepass
__global__ void xcvt_kernel(const float* __restrict__ x) {
    int idx = (blockIdx.x * 256 + threadIdx.x) * 4;
    float4 v = *(const float4*)(x + idx);
    __half2 a = __floats2half2_rn(v.x, v.y);
    __half2 b = __floats2half2_rn(v.z, v.w);
    *(uint2*)(g_xh + idx) = make_uint2(h2bits(a), h2bits(b));
}

__global__ void router_kernel(const float* __restrict__ x,
                              const float* __restrict__ gw,
                              const float* __restrict__ bias) {
    __shared__ float xs[D_DIM];
    __shared__ float logits[E_EXP];
    int t = blockIdx.x;
    const float4* xr = (const float4*)(x + (size_t)t * D_DIM);
    for (int i = threadIdx.x; i < D_DIM / 4; i += blockDim.x)
        ((float4*)xs)[i] = xr[i];
    __syncthreads();

    int e = threadIdx.x >> 2;
    int g = threadIdx.x & 3;
    const float4* wrow = (const float4*)(gw + (size_t)e * D_DIM);
    float s = 0.f;
    for (int d4 = g; d4 < D_DIM / 4; d4 += 4) {
        float4 a = ((const float4*)xs)[d4];
        float4 b = wrow[d4];
        s += a.x * b.x + a.y * b.y + a.z * b.z + a.w * b.w;
    }
    s += __shfl_down_sync(0xffffffffu, s, 2, 4);
    s += __shfl_down_sync(0xffffffffu, s, 1, 4);
    if (g == 0) logits[e] = s + bias[e];
    __syncthreads();

    if (threadIdx.x == 0) {
        float v[TOPK]; int idx[TOPK];
        unsigned used = 0;
        for (int k = 0; k < TOPK; k++) {
            float best = -3.4e38f; int bi = 0;
            for (int j = 0; j < E_EXP; j++) {
                if (used & (1u << j)) continue;
                if (logits[j] > best) { best = logits[j]; bi = j; }
            }
            used |= 1u << bi; v[k] = best; idx[k] = bi;
        }
        float ex[TOPK], sum = 0.f;
        for (int k = 0; k < TOPK; k++) { ex[k] = __expf(v[k] - v[0]); sum += ex[k]; }
        float inv = 1.f / sum;
        for (int k = 0; k < TOPK; k++) {
            int ek = idx[k];
            int slot = atomicAdd(&g_cnt[ek], 1);
            g_pairs[ek * T_TOK + slot] = t * TOPK + k;
            g_w[t * TOPK + k] = ex[k] * inv;
        }
    }
}

// stats + compact work-list builder
__global__ void stats_kernel(float* __restrict__ tail) {
    int e = threadIdx.x;
    float c = (float)g_cnt[e];
    float mean = (float)(T_TOK * TOPK) / E_EXP;
    float d = c - mean;
    float v = d * d;
    for (int o = 16; o > 0; o >>= 1) v += __shfl_down_sync(0xffffffffu, v, o);
    if (tail) {
        tail[e] = c;
        if (e == 0) tail[E_EXP] = sqrtf(v / E_EXP) / (mean + 1e-6f);
    }
    if (threadIdx.x == 0) {
        int n = 0;
        for (int z = 0; z < E_EXP; ++z) {
            int tiles = (g_cnt[z] + 127) >> 7;
            for (int mt = 0; mt < tiles && n < MAXW; ++mt)
                g_work[n++] = (z << 16) | mt;
        }
        for (int mt = 0; mt < T_TOK / 128 && n < MAXW; ++mt)
            g_work[n++] = (E_EXP << 16) | mt;
        g_nwork = n;
    }
}

// ================= gate+up warp-MMA (fp16 1-term, 64x32 warp tiles, K-split pairs) =================
// CTA 128M x 64N(F), 512 threads. 8 gate warps + 8 up warps.
// Within each matrix group: 4 positions (2M x 2N of 64x32) x 2 K-groups; combine in epilogue.
#define APITCH 144
#define GU_A   0
#define GU_BG  18432
#define GU_BU  27648
#define GU_STAGE 36864
#define GU_SMEM (1024 + 2 * GU_STAGE)   // 74752

__global__ void __launch_bounds__(512, 1)
gu_mma(const float* __restrict__ Wg, const float* __restrict__ Wu,
       const float* __restrict__ wsg, const float* __restrict__ wsu) {
    extern __shared__ char smem[];
    int tid = threadIdx.x;
    int wi = blockIdx.y;
    if (wi >= g_nwork) return;
    int code = g_work[wi];
    int z = code >> 16;
    int mt = code & 0xffff;
    bool SH = (z == E_EXP);
    int ne = SH ? T_TOK : g_cnt[z];
    int m0 = mt * 128;
    int n0 = blockIdx.x * 64;
    const float* wgp = SH ? wsg : (Wg + (size_t)z * F_DIM * D_DIM);
    const float* wup = SH ? wsu : (Wu + (size_t)z * F_DIM * D_DIM);

    int* s_pair = (int*)smem;
    int* s_src  = (int*)(smem + 512);
    if (tid < 128) {
        int m = m0 + tid;
        int pair = SH ? m : ((m < ne) ? g_pairs[z * T_TOK + m] : g_pairs[z * T_TOK]);
        s_pair[tid] = pair;
        s_src[tid]  = SH ? m : (pair >> 2);
    }
    __syncthreads();

    // A loader: fp16 source, 128 rows x 128B/chunk -> 1024 uint4, 2/thread
    const __half* haptr[2];
    unsigned soA[2];
#pragma unroll
    for (int j = 0; j < 2; ++j) {
        int idx = tid + 512 * j;
        int row = idx >> 3, c8 = idx & 7;
        haptr[j] = g_xh + (size_t)s_src[row] * D_DIM + c8 * 8;
        soA[j]   = GU_A + row * APITCH + c8 * 16;
    }
    // B loader: gate rows (j=0,1) + up rows (j=2,3), fp32, 4 f4/thread
    const float* bptr[4];
    unsigned soB[4];
#pragma unroll
    for (int j = 0; j < 4; ++j) {
        int idx = tid + 512 * j;
        bool isu = idx >= 1024;
        int li = idx & 1023;
        int row = li >> 4, c4 = li & 15;
        bptr[j] = (isu ? wup : wgp) + (size_t)(n0 + row) * D_DIM + c4 * 4;
        soB[j]  = (isu ? GU_BU : GU_BG) + row * APITCH + c4 * 8;
    }

    const int wid = tid >> 5, lane = tid & 31;
    const bool isUp = wid >= 8;
    const int grp = wid & 7;
    const int pos = grp & 3;           // 4 positions of 64x32
    const int kg  = grp >> 2;          // K-group 0/1
    const int wm = pos >> 1, wn = pos & 1;

    float acc[4][4][4] = {};

    uint4  rha[2];
    float4 rwb[4];
#pragma unroll
    for (int j = 0; j < 2; ++j) rha[j] = *(const uint4*)(haptr[j]);
#pragma unroll
    for (int j = 0; j < 4; ++j) rwb[j] = *(const float4*)(bptr[j]);

    const uint32_t a_row = wm * 64 + (lane & 15);
    const uint32_t a_colb = (lane >> 4) * 16;
    const uint32_t b_row = wn * 32 + ((lane >> 3) >> 1) * 8 + (lane & 7);
    const uint32_t b_colb = ((lane >> 3) & 1) * 16;

#define GU_STORE(BUF) do { \
    char* b_ = (BUF); \
    _Pragma("unroll") \
    for (int j = 0; j < 2; ++j) \
        *(uint4*)(b_ + soA[j]) = rha[j]; \
    _Pragma("unroll") \
    for (int j = 0; j < 4; ++j) \
        h16_store4(b_ + soB[j], rwb[j]); \
} while (0)

    GU_STORE(smem + 1024);
    __syncthreads();

    for (int ch = 0; ch < 16; ++ch) {
        if (ch < 15) {
            int k0 = (ch + 1) * 64;
#pragma unroll
            for (int j = 0; j < 2; ++j) rha[j] = *(const uint4*)(haptr[j] + k0);
#pragma unroll
            for (int j = 0; j < 4; ++j) rwb[j] = *(const float4*)(bptr[j] + k0);
        }
        {
            char* cur = smem + 1024 + (ch & 1) * GU_STAGE;
            uint32_t abase = smem_u32(cur) + GU_A;
            uint32_t bbase = smem_u32(cur) + (isUp ? GU_BU : GU_BG);
#pragma unroll
            for (int i = 0; i < 2; ++i) {
                int ks = kg * 2 + ((i + (wid & 1)) & 1);   // staggered within K-group
                uint32_t koff = (uint32_t)ks * 32;
                uint32_t ah[4][4];
#pragma unroll
                for (int mt2 = 0; mt2 < 4; ++mt2) {
                    uint32_t ad = abase + (a_row + mt2 * 16) * APITCH + koff + a_colb;
                    ldm4(ah[mt2], ad);
                }
                uint32_t bh[8];
#pragma unroll
                for (int p2 = 0; p2 < 2; ++p2) {
                    uint32_t bd = bbase + (b_row + p2 * 16) * APITCH + koff + b_colb;
                    ldm4(&bh[p2 * 4], bd);
                }
#pragma unroll
                for (int mt2 = 0; mt2 < 4; ++mt2)
#pragma unroll
                    for (int nt = 0; nt < 4; ++nt)
                        mma16816(acc[mt2][nt], ah[mt2], &bh[nt * 2]);
            }
        }
        if (ch < 15) {
            char* nxt = smem + 1024 + ((ch + 1) & 1) * GU_STAGE;
            GU_STORE(nxt);
            __syncthreads();
        }
    }
    __syncthreads();

    // epilogue: two-phase K-group combine into stg_g / stg_u, then silu+pack+store
    float* stg_g = (float*)(smem + 1024);
    float* stg_u = stg_g + 128 * 66;
    float* my = isUp ? stg_u : stg_g;
    if (kg == 0) {
#pragma unroll
        for (int mt2 = 0; mt2 < 4; ++mt2)
#pragma unroll
            for (int nt = 0; nt < 4; ++nt) {
                int r = wm * 64 + mt2 * 16 + (lane >> 2);
                int c = wn * 32 + nt * 8 + (lane & 3) * 2;
                *(float2*)&my[r * 66 + c]       = make_float2(acc[mt2][nt][0], acc[mt2][nt][1]);
                *(float2*)&my[(r + 8) * 66 + c] = make_float2(acc[mt2][nt][2], acc[mt2][nt][3]);
            }
    }
    __syncthreads();
    if (kg == 1) {
#pragma unroll
        for (int mt2 = 0; mt2 < 4; ++mt2)
#pragma unroll
            for (int nt = 0; nt < 4; ++nt) {
                int r = wm * 64 + mt2 * 16 + (lane >> 2);
                int c = wn * 32 + nt * 8 + (lane & 3) * 2;
                float2 v0 = *(float2*)&my[r * 66 + c];
                float2 v1 = *(float2*)&my[(r + 8) * 66 + c];
                *(float2*)&my[r * 66 + c]       = make_float2(v0.x + acc[mt2][nt][0], v0.y + acc[mt2][nt][1]);
                *(float2*)&my[(r + 8) * 66 + c] = make_float2(v1.x + acc[mt2][nt][2], v1.y + acc[mt2][nt][3]);
            }
    }
    __syncthreads();

    __half* dst = SH ? g_hsp : g_hp;
    {
        int r = tid >> 2;
        int c0 = (tid & 3) * 16;
        __half* drow = dst + (size_t)s_pair[r] * F_DIM + n0 + c0;
#pragma unroll
        for (int jj = 0; jj < 16; jj += 8) {
            uint4 o;
            uint32_t* po = &o.x;
#pragma unroll
            for (int k = 0; k < 4; ++k) {
                float g0 = stg_g[r * 66 + c0 + jj + 2 * k];
                float g1 = stg_g[r * 66 + c0 + jj + 2 * k + 1];
                float u0 = stg_u[r * 66 + c0 + jj + 2 * k];
                float u1 = stg_u[r * 66 + c0 + jj + 2 * k + 1];
                float h0 = g0 / (1.f + __expf(-g0)) * u0;
                float h1 = g1 / (1.f + __expf(-g1)) * u1;
                __half2 ph = __floats2half2_rn(h0, h1);
                po[k] = h2bits(ph);
            }
            *(uint4*)(drow + jj) = o;
        }
    }
}

// ================= down warp-MMA (fp16 single-term, ks-staggered) — unchanged R14 =================
// CTA 128M x 128N(D), 512 threads, 16 warps of 32x32 (4x4). BK=64 over F.
#define DN_A 0
#define DN_B_HI 18432
#define DN_STAGE 36864
#define DN_SMEM (1024 + 2 * DN_STAGE)   // 74752

__global__ void __launch_bounds__(512, 1)
dn_mma(const float* __restrict__ Wd, const float* __restrict__ wsd,
       float* __restrict__ out) {
    extern __shared__ char smem[];
    int tid = threadIdx.x;
    int wi = blockIdx.y;
    if (wi >= g_nwork) return;
    int code = g_work[wi];
    int z = code >> 16;
    int mt = code & 0xffff;
    bool SH = (z == E_EXP);
    int ne = SH ? T_TOK : g_cnt[z];
    int m0 = mt * 128;
    int n0 = blockIdx.x * 128;
    const float* wdp = SH ? wsd : (Wd + (size_t)z * D_DIM * F_DIM);
    const __half* hsrc = SH ? g_hsp : g_hp;

    int* s_pair = (int*)smem;
    if (tid < 128) {
        int m = m0 + tid;
        s_pair[tid] = SH ? m : ((m < ne) ? g_pairs[z * T_TOK + m] : g_pairs[z * T_TOK]);
    }
    __syncthreads();

    const __half* haptr[2];
    unsigned soA[2];
#pragma unroll
    for (int j = 0; j < 2; ++j) {
        int idx = tid + 512 * j;
        int row = idx >> 3, c8 = idx & 7;
        haptr[j] = hsrc + (size_t)s_pair[row] * F_DIM + c8 * 8;
        soA[j]   = row * APITCH + c8 * 16;
    }
    const int c4 = tid & 15;
    const int rbB = tid >> 4;
    const float* bptr[4];
#pragma unroll
    for (int j = 0; j < 4; ++j)
        bptr[j] = wdp + (size_t)(n0 + rbB + 32 * j) * F_DIM + c4 * 4;

    const int wid = tid >> 5, lane = tid & 31;
    const int wm = wid >> 2, wn = wid & 3;
    const int ksrot = wid & 3;

    float acc[2][4][4] = {};

    uint4  rha[2];
    float4 rwb[4];
#pragma unroll
    for (int j = 0; j < 2; ++j) rha[j] = *(const uint4*)(haptr[j]);
#pragma unroll
    for (int j = 0; j < 4; ++j) rwb[j] = *(const float4*)(bptr[j]);

    const uint32_t a_row = wm * 32 + (lane & 15);
    const uint32_t a_colb = (lane >> 4) * 16;
    const uint32_t b_row = wn * 32 + ((lane >> 3) >> 1) * 8 + (lane & 7);
    const uint32_t b_colb = ((lane >> 3) & 1) * 16;

#define DN_STORE(BUF) do { \
    char* b_ = (BUF); \
    _Pragma("unroll") \
    for (int j = 0; j < 2; ++j) \
        *(uint4*)(b_ + DN_A + soA[j]) = rha[j]; \
    _Pragma("unroll") \
    for (int j = 0; j < 4; ++j) { \
        char* p = b_ + (rbB + 32 * j) * APITCH + c4 * 8; \
        h16_store4(p + DN_B_HI, rwb[j]); \
    } \
} while (0)

    DN_STORE(smem + 1024);
    __syncthreads();

    for (int ch = 0; ch < 32; ++ch) {
        if (ch < 31) {
            int k0 = (ch + 1) * 64;
#pragma unroll
            for (int j = 0; j < 2; ++j) rha[j] = *(const uint4*)(haptr[j] + k0);
#pragma unroll
            for (int j = 0; j < 4; ++j) rwb[j] = *(const float4*)(bptr[j] + k0);
        }
        {
            char* cur = smem + 1024 + (ch & 1) * DN_STAGE;
            uint32_t abase = smem_u32(cur) + DN_A;
            uint32_t bbase = smem_u32(cur) + DN_B_HI;
#pragma unroll
            for (int i = 0; i < 4; ++i) {
                int ks = (i + ksrot) & 3;
                uint32_t koff = (uint32_t)ks * 32;
                uint32_t ah[2][4];
#pragma unroll
                for (int mt2 = 0; mt2 < 2; ++mt2) {
                    uint32_t ad = abase + (a_row + mt2 * 16) * APITCH + koff + a_colb;
                    ldm4(ah[mt2], ad);
                }
                uint32_t bh[8];
#pragma unroll
                for (int p2 = 0; p2 < 2; ++p2) {
                    uint32_t bd = bbase + (b_row + p2 * 16) * APITCH + koff + b_colb;
                    ldm4(&bh[p2 * 4], bd);
                }
#pragma unroll
                for (int mt2 = 0; mt2 < 2; ++mt2)
#pragma unroll
                    for (int nt = 0; nt < 4; ++nt)
                        mma16816(acc[mt2][nt], ah[mt2], &bh[nt * 2]);
            }
        }
        if (ch < 31) {
            char* nxt = smem + 1024 + ((ch + 1) & 1) * DN_STAGE;
            DN_STORE(nxt);
            __syncthreads();
        }
    }
    __syncthreads();

    float* stg = (float*)(smem + 1024);
#pragma unroll
    for (int mt2 = 0; mt2 < 2; ++mt2)
#pragma unroll
        for (int nt = 0; nt < 4; ++nt) {
            int r = wm * 32 + mt2 * 16 + (lane >> 2);
            int c = wn * 32 + nt * 8 + (lane & 3) * 2;
            *(float2*)&stg[r * 132 + c]       = make_float2(acc[mt2][nt][0], acc[mt2][nt][1]);
            *(float2*)&stg[(r + 8) * 132 + c] = make_float2(acc[mt2][nt][2], acc[mt2][nt][3]);
        }
    __syncthreads();

    {
        int r = tid >> 2;
        int c0 = (tid & 3) * 32;
        float* drow;
        if (SH) drow = out + (size_t)(m0 + r) * D_DIM + n0 + c0;
        else    drow = g_y + (size_t)s_pair[r] * D_DIM + n0 + c0;
#pragma unroll
        for (int jj = 0; jj < 32; jj += 4) {
            float4 v = make_float4(stg[r * 132 + c0 + jj], stg[r * 132 + c0 + jj + 1],
                                   stg[r * 132 + c0 + jj + 2], stg[r * 132 + c0 + jj + 3]);
            *(float4*)(drow + jj) = v;
        }
    }
}

// ================= combine: out += sum_k w_k * y_pair =================
__global__ void combine_kernel(float* __restrict__ out) {
    int t = blockIdx.x;
    int c = threadIdx.x * 4;
    float4 o = *(float4*)(out + (size_t)t * D_DIM + c);
#pragma unroll
    for (int k = 0; k < TOPK; ++k) {
        int pair = t * TOPK + k;
        float w = g_w[pair];
        float4 y = *(const float4*)(g_y + (size_t)pair * D_DIM + c);
        o.x += w * y.x; o.y += w * y.y; o.z += w * y.z; o.w += w * y.w;
    }
    *(float4*)(out + (size_t)t * D_DIM + c) = o;
}

// ---------------- launch ----------------
extern "C" void kernel_launch(void* const* d_in, const int* in_sizes, int n_in,
                              void* d_out, int out_size) {
    const float* x    = (const float*)d_in[0];
    const float* gw   = (const float*)d_in[1];
    const float* bias = (const float*)d_in[2];
    const float* wg   = (const float*)d_in[3];
    const float* wu   = (const float*)d_in[4];
    const float* wd   = (const float*)d_in[5];
    const float* wsg  = (const float*)d_in[6];
    const float* wsu  = (const float*)d_in[7];
    const float* wsd  = (const float*)d_in[8];
    float* out = (float*)d_out;

    static int attr_done = 0;
    if (!attr_done) {
        cudaFuncSetAttribute(gu_mma, cudaFuncAttributeMaxDynamicSharedMemorySize, GU_SMEM);
        cudaFuncSetAttribute(dn_mma, cudaFuncAttributeMaxDynamicSharedMemorySize, DN_SMEM);
        attr_done = 1;
    }

    zero_kernel<<<1, 32>>>();
    xcvt_kernel<<<T_TOK * D_DIM / 1024, 256>>>(x);
    router_kernel<<<T_TOK, 128>>>(x, gw, bias);

    float* tail = (out_size >= T_TOK * D_DIM + E_EXP + 1) ? (out + T_TOK * D_DIM) : nullptr;
    stats_kernel<<<1, 32>>>(tail);

    // gate+up: compact work list (routed + shared)
    gu_mma<<<dim3(F_DIM / 64, MAXW), 512, GU_SMEM>>>(wg, wu, wsg, wsu);

    // down: compact work list (routed -> g_y, shared -> out)
    dn_mma<<<dim3(D_DIM / 128, MAXW), 512, DN_SMEM>>>(wd, wsd, out);

    // weighted combine
    combine_kernel<<<T_TOK, 256>>>(out);
}

// round 16
// speedup vs baseline: 1.0857x; 1.0857x over previous
#include <cuda_runtime.h>
#include <cuda_fp16.h>
#include <stdint.h>

#define T_TOK 1024
#define D_DIM 1024
#define F_DIM 2048
#define E_EXP 32
#define TOPK  4
#define NPAIR (T_TOK * TOPK)
#define MAXW  96

// ---------------- static scratch ----------------
__device__ int     g_cnt[E_EXP];
__device__ int     g_pairs[E_EXP * T_TOK];
__device__ float   g_w[NPAIR];
__device__ __half  g_xh[(size_t)T_TOK * D_DIM];    // x pre-converted fp16
__device__ __half  g_hp[(size_t)NPAIR * F_DIM];    // routed hidden fp16
__device__ __half  g_hsp[(size_t)T_TOK * F_DIM];   // shared hidden fp16
__device__ float   g_y[(size_t)NPAIR * D_DIM];     // routed per-pair down output
__device__ int     g_nwork;
__device__ int     g_work[MAXW];                   // (z<<16)|mt ; z==E_EXP -> shared

// ---------------- helpers ----------------
__device__ __forceinline__ uint32_t smem_u32(const void* p) {
    uint32_t a;
    asm("{ .reg .u64 t; cvta.to.shared.u64 t, %1; cvt.u32.u64 %0, t; }" : "=r"(a) : "l"(p));
    return a;
}
__device__ __forceinline__ void ldm4(uint32_t* r, uint32_t addr) {
    asm volatile("ldmatrix.sync.aligned.m8n8.x4.shared.b16 {%0,%1,%2,%3}, [%4];"
                 : "=r"(r[0]), "=r"(r[1]), "=r"(r[2]), "=r"(r[3]) : "r"(addr));
}
__device__ __forceinline__ void mma16816(float* d, const uint32_t* a, const uint32_t* b) {
    asm volatile("mma.sync.aligned.m16n8k16.row.col.f32.f16.f16.f32 "
                 "{%0,%1,%2,%3}, {%4,%5,%6,%7}, {%8,%9}, {%0,%1,%2,%3};"
                 : "+f"(d[0]), "+f"(d[1]), "+f"(d[2]), "+f"(d[3])
                 : "r"(a[0]), "r"(a[1]), "r"(a[2]), "r"(a[3]), "r"(b[0]), "r"(b[1]));
}
__device__ __forceinline__ uint32_t h2bits(__half2 h) {
    return *reinterpret_cast<uint32_t*>(&h);
}
__device__ __forceinline__ uint2 pack_h4(float4 v) {
    __half2 a = __floats2half2_rn(v.x, v.y);
    __half2 b = __floats2half2_rn(v.z, v.w);
    return make_uint2(h2bits(a), h2bits(b));
}
__device__ __forceinline__ void h16_store4(char* dst, float4 v) {
    *(uint2*)dst = pack_h4(v);
}

// ---------------- tiny kernels ----------------
__global__ void zero_kernel() {
    if (threadIdx.x < E_EXP) g_cnt[threadIdx.x] = 0;
}

// x -> fp16 prepass
__global__ void xcvt_kernel(const float* __restrict__ x) {
    int idx = (blockIdx.x * 256 + threadIdx.x) * 4;
    float4 v = *(const float4*)(x + idx);
    *(uint2*)(g_xh + idx) = pack_h4(v);
}

__global__ void router_kernel(const float* __restrict__ x,
                              const float* __restrict__ gw,
                              const float* __restrict__ bias) {
    __shared__ float xs[D_DIM];
    __shared__ float logits[E_EXP];
    int t = blockIdx.x;
    const float4* xr = (const float4*)(x + (size_t)t * D_DIM);
    for (int i = threadIdx.x; i < D_DIM / 4; i += blockDim.x)
        ((float4*)xs)[i] = xr[i];
    __syncthreads();

    int e = threadIdx.x >> 2;
    int g = threadIdx.x & 3;
    const float4* wrow = (const float4*)(gw + (size_t)e * D_DIM);
    float s = 0.f;
    for (int d4 = g; d4 < D_DIM / 4; d4 += 4) {
        float4 a = ((const float4*)xs)[d4];
        float4 b = wrow[d4];
        s += a.x * b.x + a.y * b.y + a.z * b.z + a.w * b.w;
    }
    s += __shfl_down_sync(0xffffffffu, s, 2, 4);
    s += __shfl_down_sync(0xffffffffu, s, 1, 4);
    if (g == 0) logits[e] = s + bias[e];
    __syncthreads();

    if (threadIdx.x == 0) {
        float v[TOPK]; int idx[TOPK];
        unsigned used = 0;
        for (int k = 0; k < TOPK; k++) {
            float best = -3.4e38f; int bi = 0;
            for (int j = 0; j < E_EXP; j++) {
                if (used & (1u << j)) continue;
                if (logits[j] > best) { best = logits[j]; bi = j; }
            }
            used |= 1u << bi; v[k] = best; idx[k] = bi;
        }
        float ex[TOPK], sum = 0.f;
        for (int k = 0; k < TOPK; k++) { ex[k] = __expf(v[k] - v[0]); sum += ex[k]; }
        float inv = 1.f / sum;
        for (int k = 0; k < TOPK; k++) {
            int ek = idx[k];
            int slot = atomicAdd(&g_cnt[ek], 1);
            g_pairs[ek * T_TOK + slot] = t * TOPK + k;
            g_w[t * TOPK + k] = ex[k] * inv;
        }
    }
}

// stats + compact work-list builder
__global__ void stats_kernel(float* __restrict__ tail) {
    int e = threadIdx.x;
    float c = (float)g_cnt[e];
    float mean = (float)(T_TOK * TOPK) / E_EXP;
    float d = c - mean;
    float v = d * d;
    for (int o = 16; o > 0; o >>= 1) v += __shfl_down_sync(0xffffffffu, v, o);
    if (tail) {
        tail[e] = c;
        if (e == 0) tail[E_EXP] = sqrtf(v / E_EXP) / (mean + 1e-6f);
    }
    if (threadIdx.x == 0) {
        int n = 0;
        for (int z = 0; z < E_EXP; ++z) {
            int tiles = (g_cnt[z] + 127) >> 7;
            for (int mt = 0; mt < tiles && n < MAXW; ++mt)
                g_work[n++] = (z << 16) | mt;
        }
        for (int mt = 0; mt < T_TOK / 128 && n < MAXW; ++mt)
            g_work[n++] = (E_EXP << 16) | mt;
        g_nwork = n;
    }
}

// ================= gate+up fused-per-warp (fp16 1-term) =================
// CTA 128M x 128N(F), 512 threads, 16 warps of 32x32 (4x4 grid),
// each warp computes BOTH gate and up accs for its tile (A frags shared).
// Register epilogue: silu(g)*u -> half2 -> gmem directly (no staging).
#define APITCH 144
#define GU_A   0
#define GU_BG  18432
#define GU_BU  36864
#define GU_STAGE 55296
#define GU_SMEM (1024 + 2 * GU_STAGE)   // 111616

__global__ void __launch_bounds__(512, 1)
gu_mma(const float* __restrict__ Wg, const float* __restrict__ Wu,
       const float* __restrict__ wsg, const float* __restrict__ wsu) {
    extern __shared__ char smem[];
    int tid = threadIdx.x;
    int wi = blockIdx.y;
    if (wi >= g_nwork) return;
    int code = g_work[wi];
    int mt = code & 0xffff;
    int z = code >> 16;
    bool SH = (z == E_EXP);
    int ne = SH ? T_TOK : g_cnt[z];
    int m0 = mt * 128;
    int n0 = blockIdx.x * 128;
    const float* wgp = SH ? wsg : (Wg + (size_t)z * F_DIM * D_DIM);
    const float* wup = SH ? wsu : (Wu + (size_t)z * F_DIM * D_DIM);

    int* s_pair = (int*)smem;
    int* s_src  = (int*)(smem + 512);
    if (tid < 128) {
        int m = m0 + tid;
        int pair = SH ? m : ((m < ne) ? g_pairs[z * T_TOK + m] : g_pairs[z * T_TOK]);
        s_pair[tid] = pair;
        s_src[tid]  = SH ? m : (pair >> 2);
    }
    __syncthreads();

    // A loader: fp16 source, 128 rows x 8 uint4/chunk -> 2 per thread
    const __half* haptr[2];
    unsigned soA[2];
#pragma unroll
    for (int j = 0; j < 2; ++j) {
        int idx = tid + 512 * j;
        int row = idx >> 3, c8 = idx & 7;
        haptr[j] = g_xh + (size_t)s_src[row] * D_DIM + c8 * 8;
        soA[j]   = GU_A + row * APITCH + c8 * 16;
    }
    // B loaders: 128 rows x 16 f4 each matrix; base + j*32 rows (immediate folds)
    const int c4 = tid & 15;
    const int rbB = tid >> 4;        // 0..31
    const float* bg0 = wgp + (size_t)(n0 + rbB) * D_DIM + c4 * 4;
    const float* bu0 = wup + (size_t)(n0 + rbB) * D_DIM + c4 * 4;
    const unsigned soB0 = rbB * APITCH + c4 * 8;

    const int wid = tid >> 5, lane = tid & 31;
    const int wm = wid >> 2, wn = wid & 3;
    const int ksrot = wid & 3;

    float accg[2][4][4] = {};
    float accu[2][4][4] = {};

    uint4 rha[2];
    uint2 hg[4], hu[4];
#pragma unroll
    for (int j = 0; j < 2; ++j) rha[j] = *(const uint4*)(haptr[j]);
#pragma unroll
    for (int j = 0; j < 4; ++j) {
        hg[j] = pack_h4(*(const float4*)(bg0 + (size_t)j * 32 * D_DIM));
        hu[j] = pack_h4(*(const float4*)(bu0 + (size_t)j * 32 * D_DIM));
    }

    const uint32_t a_row = wm * 32 + (lane & 15);
    const uint32_t a_colb = (lane >> 4) * 16;
    const uint32_t b_row = wn * 32 + ((lane >> 3) >> 1) * 8 + (lane & 7);
    const uint32_t b_colb = ((lane >> 3) & 1) * 16;

#define GU_STORE(BUF) do { \
    char* b_ = (BUF); \
    _Pragma("unroll") \
    for (int j = 0; j < 2; ++j) \
        *(uint4*)(b_ + soA[j]) = rha[j]; \
    _Pragma("unroll") \
    for (int j = 0; j < 4; ++j) { \
        *(uint2*)(b_ + GU_BG + soB0 + j * (32 * APITCH)) = hg[j]; \
        *(uint2*)(b_ + GU_BU + soB0 + j * (32 * APITCH)) = hu[j]; \
    } \
} while (0)

    GU_STORE(smem + 1024);
    __syncthreads();

    for (int ch = 0; ch < 16; ++ch) {
        if (ch < 15) {
            int k0 = (ch + 1) * 64;
#pragma unroll
            for (int j = 0; j < 2; ++j) rha[j] = *(const uint4*)(haptr[j] + k0);
#pragma unroll
            for (int j = 0; j < 4; ++j) {
                hg[j] = pack_h4(*(const float4*)(bg0 + (size_t)j * 32 * D_DIM + k0));
                hu[j] = pack_h4(*(const float4*)(bu0 + (size_t)j * 32 * D_DIM + k0));
            }
        }
        {
            char* cur = smem + 1024 + (ch & 1) * GU_STAGE;
            uint32_t abase  = smem_u32(cur) + GU_A;
            uint32_t bgbase = smem_u32(cur) + GU_BG;
            uint32_t bubase = smem_u32(cur) + GU_BU;
#pragma unroll
            for (int i = 0; i < 4; ++i) {
                int ks = (i + ksrot) & 3;
                uint32_t koff = (uint32_t)ks * 32;
                uint32_t ah[2][4];
#pragma unroll
                for (int mt2 = 0; mt2 < 2; ++mt2) {
                    uint32_t ad = abase + (a_row + mt2 * 16) * APITCH + koff + a_colb;
                    ldm4(ah[mt2], ad);
                }
                uint32_t bh[8];
                // gate
#pragma unroll
                for (int p2 = 0; p2 < 2; ++p2) {
                    uint32_t bd = bgbase + (b_row + p2 * 16) * APITCH + koff + b_colb;
                    ldm4(&bh[p2 * 4], bd);
                }
#pragma unroll
                for (int mt2 = 0; mt2 < 2; ++mt2)
#pragma unroll
                    for (int nt = 0; nt < 4; ++nt)
                        mma16816(accg[mt2][nt], ah[mt2], &bh[nt * 2]);
                // up (reuse bh regs)
#pragma unroll
                for (int p2 = 0; p2 < 2; ++p2) {
                    uint32_t bd = bubase + (b_row + p2 * 16) * APITCH + koff + b_colb;
                    ldm4(&bh[p2 * 4], bd);
                }
#pragma unroll
                for (int mt2 = 0; mt2 < 2; ++mt2)
#pragma unroll
                    for (int nt = 0; nt < 4; ++nt)
                        mma16816(accu[mt2][nt], ah[mt2], &bh[nt * 2]);
            }
        }
        if (ch < 15) {
            char* nxt = smem + 1024 + ((ch + 1) & 1) * GU_STAGE;
            GU_STORE(nxt);
            __syncthreads();
        }
    }

    // register epilogue: silu(g)*u -> half2 -> gmem (no smem staging)
    __half* dst = SH ? g_hsp : g_hp;
#pragma unroll
    for (int mt2 = 0; mt2 < 2; ++mt2)
#pragma unroll
        for (int nt = 0; nt < 4; ++nt) {
            int r  = wm * 32 + mt2 * 16 + (lane >> 2);
            int c  = wn * 32 + nt * 8 + (lane & 3) * 2;
            float g0 = accg[mt2][nt][0], g1 = accg[mt2][nt][1];
            float g2 = accg[mt2][nt][2], g3 = accg[mt2][nt][3];
            float u0 = accu[mt2][nt][0], u1 = accu[mt2][nt][1];
            float u2 = accu[mt2][nt][2], u3 = accu[mt2][nt][3];
            float h0 = g0 / (1.f + __expf(-g0)) * u0;
            float h1 = g1 / (1.f + __expf(-g1)) * u1;
            float h2 = g2 / (1.f + __expf(-g2)) * u2;
            float h3 = g3 / (1.f + __expf(-g3)) * u3;
            __half2 p0 = __floats2half2_rn(h0, h1);
            __half2 p1 = __floats2half2_rn(h2, h3);
            *(uint32_t*)(dst + (size_t)s_pair[r] * F_DIM + n0 + c)     = h2bits(p0);
            *(uint32_t*)(dst + (size_t)s_pair[r + 8] * F_DIM + n0 + c) = h2bits(p1);
        }
}

// ================= down warp-MMA (fp16 single-term, ks-staggered) — R14 exact =================
// CTA 128M x 128N(D), 512 threads, 16 warps of 32x32 (4x4). BK=64 over F.
#define DN_A 0
#define DN_B_HI 18432
#define DN_STAGE 36864
#define DN_SMEM (1024 + 2 * DN_STAGE)   // 74752

__global__ void __launch_bounds__(512, 1)
dn_mma(const float* __restrict__ Wd, const float* __restrict__ wsd,
       float* __restrict__ out) {
    extern __shared__ char smem[];
    int tid = threadIdx.x;
    int wi = blockIdx.y;
    if (wi >= g_nwork) return;
    int code = g_work[wi];
    int z = code >> 16;
    int mt = code & 0xffff;
    bool SH = (z == E_EXP);
    int ne = SH ? T_TOK : g_cnt[z];
    int m0 = mt * 128;
    int n0 = blockIdx.x * 128;
    const float* wdp = SH ? wsd : (Wd + (size_t)z * D_DIM * F_DIM);
    const __half* hsrc = SH ? g_hsp : g_hp;

    int* s_pair = (int*)smem;
    if (tid < 128) {
        int m = m0 + tid;
        s_pair[tid] = SH ? m : ((m < ne) ? g_pairs[z * T_TOK + m] : g_pairs[z * T_TOK]);
    }
    __syncthreads();

    const __half* haptr[2];
    unsigned soA[2];
#pragma unroll
    for (int j = 0; j < 2; ++j) {
        int idx = tid + 512 * j;
        int row = idx >> 3, c8 = idx & 7;
        haptr[j] = hsrc + (size_t)s_pair[row] * F_DIM + c8 * 8;
        soA[j]   = row * APITCH + c8 * 16;
    }
    const int c4 = tid & 15;
    const int rbB = tid >> 4;
    const float* bptr[4];
#pragma unroll
    for (int j = 0; j < 4; ++j)
        bptr[j] = wdp + (size_t)(n0 + rbB + 32 * j) * F_DIM + c4 * 4;

    const int wid = tid >> 5, lane = tid & 31;
    const int wm = wid >> 2, wn = wid & 3;
    const int ksrot = wid & 3;

    float acc[2][4][4] = {};

    uint4  rha[2];
    float4 rwb[4];
#pragma unroll
    for (int j = 0; j < 2; ++j) rha[j] = *(const uint4*)(haptr[j]);
#pragma unroll
    for (int j = 0; j < 4; ++j) rwb[j] = *(const float4*)(bptr[j]);

    const uint32_t a_row = wm * 32 + (lane & 15);
    const uint32_t a_colb = (lane >> 4) * 16;
    const uint32_t b_row = wn * 32 + ((lane >> 3) >> 1) * 8 + (lane & 7);
    const uint32_t b_colb = ((lane >> 3) & 1) * 16;

#define DN_STORE(BUF) do { \
    char* b_ = (BUF); \
    _Pragma("unroll") \
    for (int j = 0; j < 2; ++j) \
        *(uint4*)(b_ + DN_A + soA[j]) = rha[j]; \
    _Pragma("unroll") \
    for (int j = 0; j < 4; ++j) { \
        char* p = b_ + (rbB + 32 * j) * APITCH + c4 * 8; \
        h16_store4(p + DN_B_HI, rwb[j]); \
    } \
} while (0)

    DN_STORE(smem + 1024);
    __syncthreads();

    for (int ch = 0; ch < 32; ++ch) {
        if (ch < 31) {
            int k0 = (ch + 1) * 64;
#pragma unroll
            for (int j = 0; j < 2; ++j) rha[j] = *(const uint4*)(haptr[j] + k0);
#pragma unroll
            for (int j = 0; j < 4; ++j) rwb[j] = *(const float4*)(bptr[j] + k0);
        }
        {
            char* cur = smem + 1024 + (ch & 1) * DN_STAGE;
            uint32_t abase = smem_u32(cur) + DN_A;
            uint32_t bbase = smem_u32(cur) + DN_B_HI;
#pragma unroll
            for (int i = 0; i < 4; ++i) {
                int ks = (i + ksrot) & 3;
                uint32_t koff = (uint32_t)ks * 32;
                uint32_t ah[2][4];
#pragma unroll
                for (int mt2 = 0; mt2 < 2; ++mt2) {
                    uint32_t ad = abase + (a_row + mt2 * 16) * APITCH + koff + a_colb;
                    ldm4(ah[mt2], ad);
                }
                uint32_t bh[8];
#pragma unroll
                for (int p2 = 0; p2 < 2; ++p2) {
                    uint32_t bd = bbase + (b_row + p2 * 16) * APITCH + koff + b_colb;
                    ldm4(&bh[p2 * 4], bd);
                }
#pragma unroll
                for (int mt2 = 0; mt2 < 2; ++mt2)
#pragma unroll
                    for (int nt = 0; nt < 4; ++nt)
                        mma16816(acc[mt2][nt], ah[mt2], &bh[nt * 2]);
            }
        }
        if (ch < 31) {
            char* nxt = smem + 1024 + ((ch + 1) & 1) * DN_STAGE;
            DN_STORE(nxt);
            __syncthreads();
        }
    }
    __syncthreads();

    float* stg = (float*)(smem + 1024);
#pragma unroll
    for (int mt2 = 0; mt2 < 2; ++mt2)
#pragma unroll
        for (int nt = 0; nt < 4; ++nt) {
            int r = wm * 32 + mt2 * 16 + (lane >> 2);
            int c = wn * 32 + nt * 8 + (lane & 3) * 2;
            *(float2*)&stg[r * 132 + c]       = make_float2(acc[mt2][nt][0], acc[mt2][nt][1]);
            *(float2*)&stg[(r + 8) * 132 + c] = make_float2(acc[mt2][nt][2], acc[mt2][nt][3]);
        }
    __syncthreads();

    {
        int r = tid >> 2;
        int c0 = (tid & 3) * 32;
        float* drow;
        if (SH) drow = out + (size_t)(m0 + r) * D_DIM + n0 + c0;
        else    drow = g_y + (size_t)s_pair[r] * D_DIM + n0 + c0;
#pragma unroll
        for (int jj = 0; jj < 32; jj += 4) {
            float4 v = make_float4(stg[r * 132 + c0 + jj], stg[r * 132 + c0 + jj + 1],
                                   stg[r * 132 + c0 + jj + 2], stg[r * 132 + c0 + jj + 3]);
            *(float4*)(drow + jj) = v;
        }
    }
}

// ================= combine: out += sum_k w_k * y_pair =================
__global__ void combine_kernel(float* __restrict__ out) {
    int t = blockIdx.x;
    int c = threadIdx.x * 4;
    float4 o = *(float4*)(out + (size_t)t * D_DIM + c);
#pragma unroll
    for (int k = 0; k < TOPK; ++k) {
        int pair = t * TOPK + k;
        float w = g_w[pair];
        float4 y = *(const float4*)(g_y + (size_t)pair * D_DIM + c);
        o.x += w * y.x; o.y += w * y.y; o.z += w * y.z; o.w += w * y.w;
    }
    *(float4*)(out + (size_t)t * D_DIM + c) = o;
}

// ---------------- launch ----------------
extern "C" void kernel_launch(void* const* d_in, const int* in_sizes, int n_in,
                              void* d_out, int out_size) {
    const float* x    = (const float*)d_in[0];
    const float* gw   = (const float*)d_in[1];
    const float* bias = (const float*)d_in[2];
    const float* wg   = (const float*)d_in[3];
    const float* wu   = (const float*)d_in[4];
    const float* wd   = (const float*)d_in[5];
    const float* wsg  = (const float*)d_in[6];
    const float* wsu  = (const float*)d_in[7];
    const float* wsd  = (const float*)d_in[8];
    float* out = (float*)d_out;

    static int attr_done = 0;
    if (!attr_done) {
        cudaFuncSetAttribute(gu_mma, cudaFuncAttributeMaxDynamicSharedMemorySize, GU_SMEM);
        cudaFuncSetAttribute(dn_mma, cudaFuncAttributeMaxDynamicSharedMemorySize, DN_SMEM);
        attr_done = 1;
    }

    zero_kernel<<<1, 32>>>();
    xcvt_kernel<<<T_TOK * D_DIM / 1024, 256>>>(x);
    router_kernel<<<T_TOK, 128>>>(x, gw, bias);

    float* tail = (out_size >= T_TOK * D_DIM + E_EXP + 1) ? (out + T_TOK * D_DIM) : nullptr;
    stats_kernel<<<1, 32>>>(tail);

    // gate+up fused per warp: compact work list (routed + shared)
    gu_mma<<<dim3(F_DIM / 128, MAXW), 512, GU_SMEM>>>(wg, wu, wsg, wsu);

    // down: compact work list (routed -> g_y, shared -> out)
    dn_mma<<<dim3(D_DIM / 128, MAXW), 512, DN_SMEM>>>(wd, wsd, out);

    // weighted combine
    combine_kernel<<<T_TOK, 256>>>(out);
}

// round 17
// speedup vs baseline: 1.1132x; 1.0253x over previous
#include <cuda_runtime.h>
#include <cuda_fp16.h>
#include <stdint.h>

#define T_TOK 1024
#define D_DIM 1024
#define F_DIM 2048
#define E_EXP 32
#define TOPK  4
#define NPAIR (T_TOK * TOPK)
#define MAXW  96

// ---------------- static scratch ----------------
__device__ int     g_cnt[E_EXP];
__device__ int     g_pairs[E_EXP * T_TOK];
__device__ float   g_w[NPAIR];
__device__ __half  g_xh[(size_t)T_TOK * D_DIM];    // x pre-converted fp16
__device__ __half  g_hp[(size_t)NPAIR * F_DIM];    // routed hidden fp16
__device__ __half  g_hsp[(size_t)T_TOK * F_DIM];   // shared hidden fp16
__device__ float   g_y[(size_t)NPAIR * D_DIM];     // routed per-pair down output
__device__ int     g_nwork;
__device__ int     g_work[MAXW];                   // (z<<16)|mt ; z==E_EXP -> shared

// ---------------- helpers ----------------
__device__ __forceinline__ uint32_t smem_u32(const void* p) {
    uint32_t a;
    asm("{ .reg .u64 t; cvta.to.shared.u64 t, %1; cvt.u32.u64 %0, t; }" : "=r"(a) : "l"(p));
    return a;
}
__device__ __forceinline__ void ldm4(uint32_t* r, uint32_t addr) {
    asm volatile("ldmatrix.sync.aligned.m8n8.x4.shared.b16 {%0,%1,%2,%3}, [%4];"
                 : "=r"(r[0]), "=r"(r[1]), "=r"(r[2]), "=r"(r[3]) : "r"(addr));
}
__device__ __forceinline__ void mma16816(float* d, const uint32_t* a, const uint32_t* b) {
    asm volatile("mma.sync.aligned.m16n8k16.row.col.f32.f16.f16.f32 "
                 "{%0,%1,%2,%3}, {%4,%5,%6,%7}, {%8,%9}, {%0,%1,%2,%3};"
                 : "+f"(d[0]), "+f"(d[1]), "+f"(d[2]), "+f"(d[3])
                 : "r"(a[0]), "r"(a[1]), "r"(a[2]), "r"(a[3]), "r"(b[0]), "r"(b[1]));
}
__device__ __forceinline__ uint32_t h2bits(__half2 h) {
    return *reinterpret_cast<uint32_t*>(&h);
}
__device__ __forceinline__ uint2 pack_h4(float4 v) {
    __half2 a = __floats2half2_rn(v.x, v.y);
    __half2 b = __floats2half2_rn(v.z, v.w);
    return make_uint2(h2bits(a), h2bits(b));
}
__device__ __forceinline__ void h16_store4(char* dst, float4 v) {
    *(uint2*)dst = pack_h4(v);
}

// ---------------- tiny kernels ----------------
__global__ void zero_kernel() {
    if (threadIdx.x < E_EXP) g_cnt[threadIdx.x] = 0;
}

// x -> fp16 prepass
__global__ void xcvt_kernel(const float* __restrict__ x) {
    int idx = (blockIdx.x * 256 + threadIdx.x) * 4;
    float4 v = *(const float4*)(x + idx);
    *(uint2*)(g_xh + idx) = pack_h4(v);
}

__global__ void router_kernel(const float* __restrict__ x,
                              const float* __restrict__ gw,
                              const float* __restrict__ bias) {
    __shared__ float xs[D_DIM];
    __shared__ float logits[E_EXP];
    int t = blockIdx.x;
    const float4* xr = (const float4*)(x + (size_t)t * D_DIM);
    for (int i = threadIdx.x; i < D_DIM / 4; i += blockDim.x)
        ((float4*)xs)[i] = xr[i];
    __syncthreads();

    int e = threadIdx.x >> 2;
    int g = threadIdx.x & 3;
    const float4* wrow = (const float4*)(gw + (size_t)e * D_DIM);
    float s = 0.f;
    for (int d4 = g; d4 < D_DIM / 4; d4 += 4) {
        float4 a = ((const float4*)xs)[d4];
        float4 b = wrow[d4];
        s += a.x * b.x + a.y * b.y + a.z * b.z + a.w * b.w;
    }
    s += __shfl_down_sync(0xffffffffu, s, 2, 4);
    s += __shfl_down_sync(0xffffffffu, s, 1, 4);
    if (g == 0) logits[e] = s + bias[e];
    __syncthreads();

    if (threadIdx.x == 0) {
        float v[TOPK]; int idx[TOPK];
        unsigned used = 0;
        for (int k = 0; k < TOPK; k++) {
            float best = -3.4e38f; int bi = 0;
            for (int j = 0; j < E_EXP; j++) {
                if (used & (1u << j)) continue;
                if (logits[j] > best) { best = logits[j]; bi = j; }
            }
            used |= 1u << bi; v[k] = best; idx[k] = bi;
        }
        float ex[TOPK], sum = 0.f;
        for (int k = 0; k < TOPK; k++) { ex[k] = __expf(v[k] - v[0]); sum += ex[k]; }
        float inv = 1.f / sum;
        for (int k = 0; k < TOPK; k++) {
            int ek = idx[k];
            int slot = atomicAdd(&g_cnt[ek], 1);
            g_pairs[ek * T_TOK + slot] = t * TOPK + k;
            g_w[t * TOPK + k] = ex[k] * inv;
        }
    }
}

// stats + compact work-list builder
__global__ void stats_kernel(float* __restrict__ tail) {
    int e = threadIdx.x;
    float c = (float)g_cnt[e];
    float mean = (float)(T_TOK * TOPK) / E_EXP;
    float d = c - mean;
    float v = d * d;
    for (int o = 16; o > 0; o >>= 1) v += __shfl_down_sync(0xffffffffu, v, o);
    if (tail) {
        tail[e] = c;
        if (e == 0) tail[E_EXP] = sqrtf(v / E_EXP) / (mean + 1e-6f);
    }
    if (threadIdx.x == 0) {
        int n = 0;
        for (int z = 0; z < E_EXP; ++z) {
            int tiles = (g_cnt[z] + 127) >> 7;
            for (int mt = 0; mt < tiles && n < MAXW; ++mt)
                g_work[n++] = (z << 16) | mt;
        }
        for (int mt = 0; mt < T_TOK / 128 && n < MAXW; ++mt)
            g_work[n++] = (E_EXP << 16) | mt;
        g_nwork = n;
    }
}

// ================= gate+up fused-per-warp (fp16 1-term) — R16 exact =================
// CTA 128M x 128N(F), 512 threads, 16 warps of 32x32 (4x4 grid),
// each warp computes BOTH gate and up accs for its tile (A frags shared).
#define APITCH 144
#define GU_A   0
#define GU_BG  18432
#define GU_BU  36864
#define GU_STAGE 55296
#define GU_SMEM (1024 + 2 * GU_STAGE)   // 111616

__global__ void __launch_bounds__(512, 1)
gu_mma(const float* __restrict__ Wg, const float* __restrict__ Wu,
       const float* __restrict__ wsg, const float* __restrict__ wsu) {
    extern __shared__ char smem[];
    int tid = threadIdx.x;
    int wi = blockIdx.y;
    if (wi >= g_nwork) return;
    int code = g_work[wi];
    int mt = code & 0xffff;
    int z = code >> 16;
    bool SH = (z == E_EXP);
    int ne = SH ? T_TOK : g_cnt[z];
    int m0 = mt * 128;
    int n0 = blockIdx.x * 128;
    const float* wgp = SH ? wsg : (Wg + (size_t)z * F_DIM * D_DIM);
    const float* wup = SH ? wsu : (Wu + (size_t)z * F_DIM * D_DIM);

    int* s_pair = (int*)smem;
    int* s_src  = (int*)(smem + 512);
    if (tid < 128) {
        int m = m0 + tid;
        int pair = SH ? m : ((m < ne) ? g_pairs[z * T_TOK + m] : g_pairs[z * T_TOK]);
        s_pair[tid] = pair;
        s_src[tid]  = SH ? m : (pair >> 2);
    }
    __syncthreads();

    const __half* haptr[2];
    unsigned soA[2];
#pragma unroll
    for (int j = 0; j < 2; ++j) {
        int idx = tid + 512 * j;
        int row = idx >> 3, c8 = idx & 7;
        haptr[j] = g_xh + (size_t)s_src[row] * D_DIM + c8 * 8;
        soA[j]   = GU_A + row * APITCH + c8 * 16;
    }
    const int c4 = tid & 15;
    const int rbB = tid >> 4;        // 0..31
    const float* bg0 = wgp + (size_t)(n0 + rbB) * D_DIM + c4 * 4;
    const float* bu0 = wup + (size_t)(n0 + rbB) * D_DIM + c4 * 4;
    const unsigned soB0 = rbB * APITCH + c4 * 8;

    const int wid = tid >> 5, lane = tid & 31;
    const int wm = wid >> 2, wn = wid & 3;
    const int ksrot = wid & 3;

    float accg[2][4][4] = {};
    float accu[2][4][4] = {};

    uint4 rha[2];
    uint2 hg[4], hu[4];
#pragma unroll
    for (int j = 0; j < 2; ++j) rha[j] = *(const uint4*)(haptr[j]);
#pragma unroll
    for (int j = 0; j < 4; ++j) {
        hg[j] = pack_h4(*(const float4*)(bg0 + (size_t)j * 32 * D_DIM));
        hu[j] = pack_h4(*(const float4*)(bu0 + (size_t)j * 32 * D_DIM));
    }

    const uint32_t a_row = wm * 32 + (lane & 15);
    const uint32_t a_colb = (lane >> 4) * 16;
    const uint32_t b_row = wn * 32 + ((lane >> 3) >> 1) * 8 + (lane & 7);
    const uint32_t b_colb = ((lane >> 3) & 1) * 16;

#define GU_STORE(BUF) do { \
    char* b_ = (BUF); \
    _Pragma("unroll") \
    for (int j = 0; j < 2; ++j) \
        *(uint4*)(b_ + soA[j]) = rha[j]; \
    _Pragma("unroll") \
    for (int j = 0; j < 4; ++j) { \
        *(uint2*)(b_ + GU_BG + soB0 + j * (32 * APITCH)) = hg[j]; \
        *(uint2*)(b_ + GU_BU + soB0 + j * (32 * APITCH)) = hu[j]; \
    } \
} while (0)

    GU_STORE(smem + 1024);
    __syncthreads();

    for (int ch = 0; ch < 16; ++ch) {
        if (ch < 15) {
            int k0 = (ch + 1) * 64;
#pragma unroll
            for (int j = 0; j < 2; ++j) rha[j] = *(const uint4*)(haptr[j] + k0);
#pragma unroll
            for (int j = 0; j < 4; ++j) {
                hg[j] = pack_h4(*(const float4*)(bg0 + (size_t)j * 32 * D_DIM + k0));
                hu[j] = pack_h4(*(const float4*)(bu0 + (size_t)j * 32 * D_DIM + k0));
            }
        }
        {
            char* cur = smem + 1024 + (ch & 1) * GU_STAGE;
            uint32_t abase  = smem_u32(cur) + GU_A;
            uint32_t bgbase = smem_u32(cur) + GU_BG;
            uint32_t bubase = smem_u32(cur) + GU_BU;
#pragma unroll
            for (int i = 0; i < 4; ++i) {
                int ks = (i + ksrot) & 3;
                uint32_t koff = (uint32_t)ks * 32;
                uint32_t ah[2][4];
#pragma unroll
                for (int mt2 = 0; mt2 < 2; ++mt2) {
                    uint32_t ad = abase + (a_row + mt2 * 16) * APITCH + koff + a_colb;
                    ldm4(ah[mt2], ad);
                }
                uint32_t bh[8];
#pragma unroll
                for (int p2 = 0; p2 < 2; ++p2) {
                    uint32_t bd = bgbase + (b_row + p2 * 16) * APITCH + koff + b_colb;
                    ldm4(&bh[p2 * 4], bd);
                }
#pragma unroll
                for (int mt2 = 0; mt2 < 2; ++mt2)
#pragma unroll
                    for (int nt = 0; nt < 4; ++nt)
                        mma16816(accg[mt2][nt], ah[mt2], &bh[nt * 2]);
#pragma unroll
                for (int p2 = 0; p2 < 2; ++p2) {
                    uint32_t bd = bubase + (b_row + p2 * 16) * APITCH + koff + b_colb;
                    ldm4(&bh[p2 * 4], bd);
                }
#pragma unroll
                for (int mt2 = 0; mt2 < 2; ++mt2)
#pragma unroll
                    for (int nt = 0; nt < 4; ++nt)
                        mma16816(accu[mt2][nt], ah[mt2], &bh[nt * 2]);
            }
        }
        if (ch < 15) {
            char* nxt = smem + 1024 + ((ch + 1) & 1) * GU_STAGE;
            GU_STORE(nxt);
            __syncthreads();
        }
    }

    // register epilogue: silu(g)*u -> half2 -> gmem
    __half* dst = SH ? g_hsp : g_hp;
#pragma unroll
    for (int mt2 = 0; mt2 < 2; ++mt2)
#pragma unroll
        for (int nt = 0; nt < 4; ++nt) {
            int r  = wm * 32 + mt2 * 16 + (lane >> 2);
            int c  = wn * 32 + nt * 8 + (lane & 3) * 2;
            float g0 = accg[mt2][nt][0], g1 = accg[mt2][nt][1];
            float g2 = accg[mt2][nt][2], g3 = accg[mt2][nt][3];
            float u0 = accu[mt2][nt][0], u1 = accu[mt2][nt][1];
            float u2 = accu[mt2][nt][2], u3 = accu[mt2][nt][3];
            float h0 = g0 / (1.f + __expf(-g0)) * u0;
            float h1 = g1 / (1.f + __expf(-g1)) * u1;
            float h2 = g2 / (1.f + __expf(-g2)) * u2;
            float h3 = g3 / (1.f + __expf(-g3)) * u3;
            __half2 p0 = __floats2half2_rn(h0, h1);
            __half2 p1 = __floats2half2_rn(h2, h3);
            *(uint32_t*)(dst + (size_t)s_pair[r] * F_DIM + n0 + c)     = h2bits(p0);
            *(uint32_t*)(dst + (size_t)s_pair[r + 8] * F_DIM + n0 + c) = h2bits(p1);
        }
}

// ================= down warp-MMA (fp16 1-term) — register epilogue =================
// CTA 128M x 128N(D), 512 threads, 16 warps of 32x32 (4x4). BK=64 over F.
#define DN_A 0
#define DN_B_HI 18432
#define DN_STAGE 36864
#define DN_SMEM (1024 + 2 * DN_STAGE)   // 74752

__global__ void __launch_bounds__(512, 1)
dn_mma(const float* __restrict__ Wd, const float* __restrict__ wsd,
       float* __restrict__ out) {
    extern __shared__ char smem[];
    int tid = threadIdx.x;
    int wi = blockIdx.y;
    if (wi >= g_nwork) return;
    int code = g_work[wi];
    int z = code >> 16;
    int mt = code & 0xffff;
    bool SH = (z == E_EXP);
    int ne = SH ? T_TOK : g_cnt[z];
    int m0 = mt * 128;
    int n0 = blockIdx.x * 128;
    const float* wdp = SH ? wsd : (Wd + (size_t)z * D_DIM * F_DIM);
    const __half* hsrc = SH ? g_hsp : g_hp;

    int* s_pair = (int*)smem;
    if (tid < 128) {
        int m = m0 + tid;
        s_pair[tid] = SH ? m : ((m < ne) ? g_pairs[z * T_TOK + m] : g_pairs[z * T_TOK]);
    }
    __syncthreads();

    const __half* haptr[2];
    unsigned soA[2];
#pragma unroll
    for (int j = 0; j < 2; ++j) {
        int idx = tid + 512 * j;
        int row = idx >> 3, c8 = idx & 7;
        haptr[j] = hsrc + (size_t)s_pair[row] * F_DIM + c8 * 8;
        soA[j]   = row * APITCH + c8 * 16;
    }
    const int c4 = tid & 15;
    const int rbB = tid >> 4;
    const float* bptr[4];
#pragma unroll
    for (int j = 0; j < 4; ++j)
        bptr[j] = wdp + (size_t)(n0 + rbB + 32 * j) * F_DIM + c4 * 4;

    const int wid = tid >> 5, lane = tid & 31;
    const int wm = wid >> 2, wn = wid & 3;
    const int ksrot = wid & 3;

    float acc[2][4][4] = {};

    uint4  rha[2];
    float4 rwb[4];
#pragma unroll
    for (int j = 0; j < 2; ++j) rha[j] = *(const uint4*)(haptr[j]);
#pragma unroll
    for (int j = 0; j < 4; ++j) rwb[j] = *(const float4*)(bptr[j]);

    const uint32_t a_row = wm * 32 + (lane & 15);
    const uint32_t a_colb = (lane >> 4) * 16;
    const uint32_t b_row = wn * 32 + ((lane >> 3) >> 1) * 8 + (lane & 7);
    const uint32_t b_colb = ((lane >> 3) & 1) * 16;

#define DN_STORE(BUF) do { \
    char* b_ = (BUF); \
    _Pragma("unroll") \
    for (int j = 0; j < 2; ++j) \
        *(uint4*)(b_ + DN_A + soA[j]) = rha[j]; \
    _Pragma("unroll") \
    for (int j = 0; j < 4; ++j) { \
        char* p = b_ + (rbB + 32 * j) * APITCH + c4 * 8; \
        h16_store4(p + DN_B_HI, rwb[j]); \
    } \
} while (0)

    DN_STORE(smem + 1024);
    __syncthreads();

    for (int ch = 0; ch < 32; ++ch) {
        if (ch < 31) {
            int k0 = (ch + 1) * 64;
#pragma unroll
            for (int j = 0; j < 2; ++j) rha[j] = *(const uint4*)(haptr[j] + k0);
#pragma unroll
            for (int j = 0; j < 4; ++j) rwb[j] = *(const float4*)(bptr[j] + k0);
        }
        {
            char* cur = smem + 1024 + (ch & 1) * DN_STAGE;
            uint32_t abase = smem_u32(cur) + DN_A;
            uint32_t bbase = smem_u32(cur) + DN_B_HI;
#pragma unroll
            for (int i = 0; i < 4; ++i) {
                int ks = (i + ksrot) & 3;
                uint32_t koff = (uint32_t)ks * 32;
                uint32_t ah[2][4];
#pragma unroll
                for (int mt2 = 0; mt2 < 2; ++mt2) {
                    uint32_t ad = abase + (a_row + mt2 * 16) * APITCH + koff + a_colb;
                    ldm4(ah[mt2], ad);
                }
                uint32_t bh[8];
#pragma unroll
                for (int p2 = 0; p2 < 2; ++p2) {
                    uint32_t bd = bbase + (b_row + p2 * 16) * APITCH + koff + b_colb;
                    ldm4(&bh[p2 * 4], bd);
                }
#pragma unroll
                for (int mt2 = 0; mt2 < 2; ++mt2)
#pragma unroll
                    for (int nt = 0; nt < 4; ++nt)
                        mma16816(acc[mt2][nt], ah[mt2], &bh[nt * 2]);
            }
        }
        if (ch < 31) {
            char* nxt = smem + 1024 + ((ch + 1) & 1) * DN_STAGE;
            DN_STORE(nxt);
            __syncthreads();
        }
    }

    // register epilogue: direct float2 stores (32B-sector aligned per lane quad)
    float* base = SH ? out : g_y;
#pragma unroll
    for (int mt2 = 0; mt2 < 2; ++mt2)
#pragma unroll
        for (int nt = 0; nt < 4; ++nt) {
            int r = wm * 32 + mt2 * 16 + (lane >> 2);
            int c = wn * 32 + nt * 8 + (lane & 3) * 2;
            size_t row0 = SH ? (size_t)(m0 + r)     : (size_t)s_pair[r];
            size_t row1 = SH ? (size_t)(m0 + r + 8) : (size_t)s_pair[r + 8];
            *(float2*)(base + row0 * D_DIM + n0 + c) = make_float2(acc[mt2][nt][0], acc[mt2][nt][1]);
            *(float2*)(base + row1 * D_DIM + n0 + c) = make_float2(acc[mt2][nt][2], acc[mt2][nt][3]);
        }
}

// ================= combine: out += sum_k w_k * y_pair =================
__global__ void combine_kernel(float* __restrict__ out) {
    int t = blockIdx.x;
    int c = threadIdx.x * 4;
    float4 o = *(float4*)(out + (size_t)t * D_DIM + c);
#pragma unroll
    for (int k = 0; k < TOPK; ++k) {
        int pair = t * TOPK + k;
        float w = g_w[pair];
        float4 y = *(const float4*)(g_y + (size_t)pair * D_DIM + c);
        o.x += w * y.x; o.y += w * y.y; o.z += w * y.z; o.w += w * y.w;
    }
    *(float4*)(out + (size_t)t * D_DIM + c) = o;
}

// ---------------- launch ----------------
extern "C" void kernel_launch(void* const* d_in, const int* in_sizes, int n_in,
                              void* d_out, int out_size) {
    const float* x    = (const float*)d_in[0];
    const float* gw   = (const float*)d_in[1];
    const float* bias = (const float*)d_in[2];
    const float* wg   = (const float*)d_in[3];
    const float* wu   = (const float*)d_in[4];
    const float* wd   = (const float*)d_in[5];
    const float* wsg  = (const float*)d_in[6];
    const float* wsu  = (const float*)d_in[7];
    const float* wsd  = (const float*)d_in[8];
    float* out = (float*)d_out;

    static int attr_done = 0;
    if (!attr_done) {
        cudaFuncSetAttribute(gu_mma, cudaFuncAttributeMaxDynamicSharedMemorySize, GU_SMEM);
        cudaFuncSetAttribute(dn_mma, cudaFuncAttributeMaxDynamicSharedMemorySize, DN_SMEM);
        attr_done = 1;
    }

    zero_kernel<<<1, 32>>>();
    xcvt_kernel<<<T_TOK * D_DIM / 1024, 256>>>(x);
    router_kernel<<<T_TOK, 128>>>(x, gw, bias);

    float* tail = (out_size >= T_TOK * D_DIM + E_EXP + 1) ? (out + T_TOK * D_DIM) : nullptr;
    stats_kernel<<<1, 32>>>(tail);

    // gate+up fused per warp: compact work list (routed + shared)
    gu_mma<<<dim3(F_DIM / 128, MAXW), 512, GU_SMEM>>>(wg, wu, wsg, wsu);

    // down: compact work list (routed -> g_y, shared -> out)
    dn_mma<<<dim3(D_DIM / 128, MAXW), 512, DN_SMEM>>>(wd, wsd, out);

    // weighted combine
    combine_kernel<<<T_TOK, 256>>>(out);
}